// round 2
// baseline (speedup 1.0000x reference)
#include <cuda_runtime.h>

static constexpr int NL   = 4096;    // coarse points
static constexpr int NH   = 16384;   // fine points
static constexpr int NF   = 256;     // features
static constexpr int TPB  = 128;     // threads per block == fine points per block
static constexpr int HALF = 2048;    // pos_l chunk staged in shared (32 KB as float4)

__global__ __launch_bounds__(TPB, 1)
void knn_interp_kernel(const float* __restrict__ x,
                       const float* __restrict__ pos_l,
                       const float* __restrict__ pos_h,
                       float* __restrict__ out)
{
    __shared__ float4 sL[HALF];        // (-2*lx, -2*ly, -2*lz, |l|^2)
    __shared__ int    sIdx[TPB][3];
    __shared__ float  sW[TPB][4];

    const int tid = threadIdx.x;
    const int h   = blockIdx.x * TPB + tid;

    const float hx = pos_h[3*h+0];
    const float hy = pos_h[3*h+1];
    const float hz = pos_h[3*h+2];

    // top-3 by score = |l|^2 - 2 h.l  (same ordering as reference's d2 expansion)
    float s0 = 3.4e38f, s1 = 3.4e38f, s2 = 3.4e38f;
    int   i0 = 0, i1 = 0, i2 = 0;

    #pragma unroll 1
    for (int half = 0; half < NL / HALF; ++half) {
        const int base = half * HALF;
        __syncthreads();   // protect sL before overwrite (no-op cost on first iter)
        for (int j = tid; j < HALF; j += TPB) {
            const int g = base + j;
            const float lx = pos_l[3*g+0];
            const float ly = pos_l[3*g+1];
            const float lz = pos_l[3*g+2];
            sL[j] = make_float4(-2.0f*lx, -2.0f*ly, -2.0f*lz,
                                fmaf(lx, lx, fmaf(ly, ly, lz*lz)));
        }
        __syncthreads();

        #pragma unroll 8
        for (int j = 0; j < HALF; ++j) {
            const float4 m = sL[j];
            const float s = fmaf(m.x, hx, fmaf(m.y, hy, fmaf(m.z, hz, m.w)));
            if (s < s2) {                       // rare path (~21 insertions / 4096)
                const int g = base + j;
                if (s < s1) {
                    s2 = s1; i2 = i1;
                    if (s < s0) { s1 = s0; i1 = i0; s0 = s; i0 = g; }
                    else        { s1 = s;  i1 = g; }
                } else { s2 = s; i2 = g; }
            }
        }
    }

    // Exact squared distances for the 3 selected (matches reference recompute),
    // inverse-distance weights, pre-normalized.
    const int id[3] = {i0, i1, i2};
    float w[3];
    float wsum = 0.0f;
    #pragma unroll
    for (int k = 0; k < 3; ++k) {
        const float lx = pos_l[3*id[k]+0];   // 48KB table: L1/L2 hit
        const float ly = pos_l[3*id[k]+1];
        const float lz = pos_l[3*id[k]+2];
        const float dx = hx - lx, dy = hy - ly, dz = hz - lz;
        const float d2 = fmaf(dx, dx, fmaf(dy, dy, dz*dz));
        const float wk = 1.0f / fmaxf(d2, 1e-16f);
        w[k] = wk;
        wsum += wk;
    }
    const float inv = 1.0f / wsum;
    sIdx[tid][0] = id[0]; sIdx[tid][1] = id[1]; sIdx[tid][2] = id[2];
    sW[tid][0] = w[0]*inv; sW[tid][1] = w[1]*inv; sW[tid][2] = w[2]*inv;
    __syncthreads();

    // Phase B: gather + weighted sum. One warp per fine point, float4-coalesced.
    const int warp = tid >> 5, lane = tid & 31;
    const float4* __restrict__ x4 = reinterpret_cast<const float4*>(x);
    float4* __restrict__ o4 = reinterpret_cast<float4*>(out);
    const int rowq = NF / 4;   // 64 float4 per feature row

    for (int p = warp; p < TPB; p += 4) {
        const int hh = blockIdx.x * TPB + p;
        const int a = sIdx[p][0], b = sIdx[p][1], c = sIdx[p][2];
        const float w0 = sW[p][0], w1 = sW[p][1], w2 = sW[p][2];
        const float4* __restrict__ ra = x4 + a * rowq;
        const float4* __restrict__ rb = x4 + b * rowq;
        const float4* __restrict__ rc = x4 + c * rowq;
        float4* __restrict__ ro = o4 + hh * rowq;
        #pragma unroll
        for (int ch = lane; ch < rowq; ch += 32) {
            const float4 va = ra[ch];
            const float4 vb = rb[ch];
            const float4 vc = rc[ch];
            float4 r;
            r.x = fmaf(w2, vc.x, fmaf(w1, vb.x, w0 * va.x));
            r.y = fmaf(w2, vc.y, fmaf(w1, vb.y, w0 * va.y));
            r.z = fmaf(w2, vc.z, fmaf(w1, vb.z, w0 * va.z));
            r.w = fmaf(w2, vc.w, fmaf(w1, vb.w, w0 * va.w));
            ro[ch] = r;
        }
    }
}

extern "C" void kernel_launch(void* const* d_in, const int* in_sizes, int n_in,
                              void* d_out, int out_size) {
    // Map inputs by element count for robustness:
    //   x: 4096*256 = 1048576, pos_l: 4096*3 = 12288, pos_h: 16384*3 = 49152
    const float* x     = nullptr;
    const float* pos_l = nullptr;
    const float* pos_h = nullptr;
    for (int i = 0; i < n_in; ++i) {
        if      (in_sizes[i] == NL * NF) x     = (const float*)d_in[i];
        else if (in_sizes[i] == NL * 3)  pos_l = (const float*)d_in[i];
        else if (in_sizes[i] == NH * 3)  pos_h = (const float*)d_in[i];
    }
    float* out = (float*)d_out;
    knn_interp_kernel<<<NH / TPB, TPB>>>(x, pos_l, pos_h, out);
}

// round 3
// speedup vs baseline: 2.3923x; 2.3923x over previous
#include <cuda_runtime.h>

static constexpr int NL   = 4096;    // coarse points
static constexpr int NH   = 16384;   // fine points
static constexpr int NF   = 256;     // features
static constexpr int PPB  = 128;     // fine points per block
static constexpr int SUBS = 4;       // threads cooperating per point
static constexpr int TPB  = PPB * SUBS;   // 512
static constexpr int HALF = 2048;    // pos_l chunk staged in shared (32 KB as float4)
static constexpr int WIN  = HALF / SUBS;  // 512 candidates per sub per half

__global__ __launch_bounds__(TPB, 1)
void knn_interp_kernel(const float* __restrict__ x,
                       const float* __restrict__ pos_l,
                       const float* __restrict__ pos_h,
                       float* __restrict__ out)
{
    __shared__ float4 sL[HALF];            // (-2*lx, -2*ly, -2*lz, |l|^2)  32 KB
    __shared__ float  sMs[SUBS][PPB][3];   // partial top-3 scores           6 KB
    __shared__ int    sMi[SUBS][PPB][3];   // partial top-3 indices          6 KB
    __shared__ int    sIdx[PPB][3];
    __shared__ float  sW[PPB][3];

    const int tid = threadIdx.x;
    const int sub = tid >> 7;          // 0..3 : which candidate slice
    const int p   = tid & (PPB - 1);   // 0..127 : which fine point
    const int h   = blockIdx.x * PPB + p;

    const float hx = pos_h[3*h+0];
    const float hy = pos_h[3*h+1];
    const float hz = pos_h[3*h+2];

    // Partial top-3 by score = |l|^2 - 2 h.l  (same ordering as d2 expansion)
    float s0 = 3.4e38f, s1 = 3.4e38f, s2 = 3.4e38f;
    int   i0 = 0, i1 = 0, i2 = 0;

    #pragma unroll 1
    for (int half = 0; half < NL / HALF; ++half) {
        const int base = half * HALF;
        __syncthreads();
        for (int j = tid; j < HALF; j += TPB) {
            const int g = base + j;
            const float lx = pos_l[3*g+0];
            const float ly = pos_l[3*g+1];
            const float lz = pos_l[3*g+2];
            sL[j] = make_float4(-2.0f*lx, -2.0f*ly, -2.0f*lz,
                                fmaf(lx, lx, fmaf(ly, ly, lz*lz)));
        }
        __syncthreads();

        const int jb = sub * WIN;   // all lanes of a warp share jb -> LDS broadcast
        #pragma unroll 8
        for (int jj = 0; jj < WIN; ++jj) {
            const int j = jb + jj;
            const float4 m = sL[j];
            const float s = fmaf(m.x, hx, fmaf(m.y, hy, fmaf(m.z, hz, m.w)));
            if (s < s2) {
                const int g = base + j;
                if (s < s1) {
                    s2 = s1; i2 = i1;
                    if (s < s0) { s1 = s0; i1 = i0; s0 = s; i0 = g; }
                    else        { s1 = s;  i1 = g; }
                } else { s2 = s; i2 = g; }
            }
        }
    }

    sMs[sub][p][0] = s0; sMs[sub][p][1] = s1; sMs[sub][p][2] = s2;
    sMi[sub][p][0] = i0; sMi[sub][p][1] = i1; sMi[sub][p][2] = i2;
    __syncthreads();

    // Merge 4 partial top-3s -> final top-3; compute exact-d2 weights.
    // Threads tid<PPB have p==tid, so (hx,hy,hz) already hold this point's coords.
    if (tid < PPB) {
        float b0 = 3.4e38f, b1 = 3.4e38f, b2 = 3.4e38f;
        int   j0 = 0, j1 = 0, j2 = 0;
        #pragma unroll
        for (int ss = 0; ss < SUBS; ++ss) {
            #pragma unroll
            for (int k = 0; k < 3; ++k) {
                const float s = sMs[ss][tid][k];
                const int   g = sMi[ss][tid][k];
                if (s < b2) {
                    if (s < b1) {
                        b2 = b1; j2 = j1;
                        if (s < b0) { b1 = b0; j1 = j0; b0 = s; j0 = g; }
                        else        { b1 = s;  j1 = g; }
                    } else { b2 = s; j2 = g; }
                }
            }
        }
        // Exact squared distances for the 3 selected (matches reference recompute)
        const int id[3] = {j0, j1, j2};
        float w[3];
        float wsum = 0.0f;
        #pragma unroll
        for (int k = 0; k < 3; ++k) {
            const float lx = pos_l[3*id[k]+0];
            const float ly = pos_l[3*id[k]+1];
            const float lz = pos_l[3*id[k]+2];
            const float dx = hx - lx, dy = hy - ly, dz = hz - lz;
            const float d2 = fmaf(dx, dx, fmaf(dy, dy, dz*dz));
            const float wk = 1.0f / fmaxf(d2, 1e-16f);
            w[k] = wk;
            wsum += wk;
        }
        const float inv = 1.0f / wsum;
        sIdx[tid][0] = id[0]; sIdx[tid][1] = id[1]; sIdx[tid][2] = id[2];
        sW[tid][0] = w[0]*inv; sW[tid][1] = w[1]*inv; sW[tid][2] = w[2]*inv;
    }
    __syncthreads();

    // Phase B: gather + weighted sum. One warp per fine point, float4-coalesced.
    const int warp = tid >> 5, lane = tid & 31;   // 16 warps
    const float4* __restrict__ x4 = reinterpret_cast<const float4*>(x);
    float4* __restrict__ o4 = reinterpret_cast<float4*>(out);
    const int rowq = NF / 4;   // 64 float4 per feature row

    for (int pp = warp; pp < PPB; pp += 16) {
        const int hh = blockIdx.x * PPB + pp;
        const int a = sIdx[pp][0], b = sIdx[pp][1], c = sIdx[pp][2];
        const float w0 = sW[pp][0], w1 = sW[pp][1], w2 = sW[pp][2];
        const float4* __restrict__ ra = x4 + a * rowq;
        const float4* __restrict__ rb = x4 + b * rowq;
        const float4* __restrict__ rc = x4 + c * rowq;
        float4* __restrict__ ro = o4 + hh * rowq;
        #pragma unroll
        for (int ch = lane; ch < rowq; ch += 32) {
            const float4 va = ra[ch];
            const float4 vb = rb[ch];
            const float4 vc = rc[ch];
            float4 r;
            r.x = fmaf(w2, vc.x, fmaf(w1, vb.x, w0 * va.x));
            r.y = fmaf(w2, vc.y, fmaf(w1, vb.y, w0 * va.y));
            r.z = fmaf(w2, vc.z, fmaf(w1, vb.z, w0 * va.z));
            r.w = fmaf(w2, vc.w, fmaf(w1, vb.w, w0 * va.w));
            ro[ch] = r;
        }
    }
}

extern "C" void kernel_launch(void* const* d_in, const int* in_sizes, int n_in,
                              void* d_out, int out_size) {
    // Map inputs by element count:
    //   x: 4096*256 = 1048576, pos_l: 4096*3 = 12288, pos_h: 16384*3 = 49152
    const float* x     = nullptr;
    const float* pos_l = nullptr;
    const float* pos_h = nullptr;
    for (int i = 0; i < n_in; ++i) {
        if      (in_sizes[i] == NL * NF) x     = (const float*)d_in[i];
        else if (in_sizes[i] == NL * 3)  pos_l = (const float*)d_in[i];
        else if (in_sizes[i] == NH * 3)  pos_h = (const float*)d_in[i];
    }
    float* out = (float*)d_out;
    knn_interp_kernel<<<NH / PPB, TPB>>>(x, pos_l, pos_h, out);
}

// round 5
// speedup vs baseline: 2.6986x; 1.1280x over previous
#include <cuda_runtime.h>

static constexpr int NL   = 4096;    // coarse points
static constexpr int NH   = 16384;   // fine points
static constexpr int NF   = 256;     // features
static constexpr int PPB  = 128;     // fine points per block
static constexpr int SUBS = 8;       // threads cooperating per point
static constexpr int TPB  = PPB * SUBS;   // 1024
static constexpr int HALF = 2048;    // pos_l chunk staged in shared (32 KB as float4)
static constexpr int WIN  = HALF / SUBS;  // 256 candidates per sub per half

__global__ __launch_bounds__(TPB, 1)
void knn_interp_kernel(const float* __restrict__ x,
                       const float* __restrict__ pos_l,
                       const float* __restrict__ pos_h,
                       float* __restrict__ out)
{
    // 32 KB buffer: holds sL during the scan, then is reused (after a barrier)
    // for the per-sub partial top-3 merge arrays (8*128*3*4 B = 12 KB each).
    __shared__ __align__(16) char smemBuf[HALF * 16];
    __shared__ int   sIdx[PPB][3];
    __shared__ float sW[PPB][3];

    float4* sL  = reinterpret_cast<float4*>(smemBuf);
    float (*sMs)[PPB][3] = reinterpret_cast<float (*)[PPB][3]>(smemBuf);
    int   (*sMi)[PPB][3] = reinterpret_cast<int   (*)[PPB][3]>(smemBuf + SUBS*PPB*3*4);

    const int tid = threadIdx.x;
    const int sub = tid >> 7;          // 0..7 : candidate slice
    const int p   = tid & (PPB - 1);   // 0..127 : fine point within block
    const int h   = blockIdx.x * PPB + p;

    const float hx = pos_h[3*h+0];
    const float hy = pos_h[3*h+1];
    const float hz = pos_h[3*h+2];

    // Partial top-3 by score = |l|^2 - 2 h.l (same ordering as d2 expansion)
    float s0 = 3.4e38f, s1 = 3.4e38f, s2 = 3.4e38f;
    int   i0 = 0, i1 = 0, i2 = 0;

    #pragma unroll 1
    for (int half = 0; half < NL / HALF; ++half) {
        const int base = half * HALF;
        __syncthreads();
        for (int j = tid; j < HALF; j += TPB) {
            const int g = base + j;
            const float lx = pos_l[3*g+0];
            const float ly = pos_l[3*g+1];
            const float lz = pos_l[3*g+2];
            sL[j] = make_float4(-2.0f*lx, -2.0f*ly, -2.0f*lz,
                                fmaf(lx, lx, fmaf(ly, ly, lz*lz)));
        }
        __syncthreads();

        const int jb = sub * WIN;   // all lanes of a warp share jb -> LDS broadcast
        #pragma unroll 8
        for (int jj = 0; jj < WIN; ++jj) {
            const int j = jb + jj;
            const float4 m = sL[j];
            const float s = fmaf(m.x, hx, fmaf(m.y, hy, fmaf(m.z, hz, m.w)));
            if (s < s2) {
                const int g = base + j;
                if (s < s1) {
                    s2 = s1; i2 = i1;
                    if (s < s0) { s1 = s0; i1 = i0; s0 = s; i0 = g; }
                    else        { s1 = s;  i1 = g; }
                } else { s2 = s; i2 = g; }
            }
        }
    }

    __syncthreads();   // all reads of sL done -> safe to alias as merge buffers
    sMs[sub][p][0] = s0; sMs[sub][p][1] = s1; sMs[sub][p][2] = s2;
    sMi[sub][p][0] = i0; sMi[sub][p][1] = i1; sMi[sub][p][2] = i2;
    __syncthreads();

    // Merge 8 partial top-3s -> final top-3; exact-d2 weights.
    // Threads tid<PPB have p==tid, so (hx,hy,hz) already hold this point's coords.
    if (tid < PPB) {
        float b0 = 3.4e38f, b1 = 3.4e38f, b2 = 3.4e38f;
        int   j0 = 0, j1 = 0, j2 = 0;
        #pragma unroll
        for (int ss = 0; ss < SUBS; ++ss) {
            #pragma unroll
            for (int k = 0; k < 3; ++k) {
                const float s = sMs[ss][tid][k];
                const int   g = sMi[ss][tid][k];
                if (s < b2) {
                    if (s < b1) {
                        b2 = b1; j2 = j1;
                        if (s < b0) { b1 = b0; j1 = j0; b0 = s; j0 = g; }
                        else        { b1 = s;  j1 = g; }
                    } else { b2 = s; j2 = g; }
                }
            }
        }
        // Exact squared distances for the 3 selected (matches reference recompute)
        const int id[3] = {j0, j1, j2};
        float w[3];
        float wsum = 0.0f;
        #pragma unroll
        for (int k = 0; k < 3; ++k) {
            const float lx = pos_l[3*id[k]+0];
            const float ly = pos_l[3*id[k]+1];
            const float lz = pos_l[3*id[k]+2];
            const float dx = hx - lx, dy = hy - ly, dz = hz - lz;
            const float d2 = fmaf(dx, dx, fmaf(dy, dy, dz*dz));
            const float wk = 1.0f / fmaxf(d2, 1e-16f);
            w[k] = wk;
            wsum += wk;
        }
        const float inv = 1.0f / wsum;
        sIdx[tid][0] = id[0]; sIdx[tid][1] = id[1]; sIdx[tid][2] = id[2];
        sW[tid][0] = w[0]*inv; sW[tid][1] = w[1]*inv; sW[tid][2] = w[2]*inv;
    }
    __syncthreads();

    // Phase B: gather + weighted sum. One warp per fine point, float4-coalesced.
    const int warp = tid >> 5, lane = tid & 31;   // 32 warps
    const float4* __restrict__ x4 = reinterpret_cast<const float4*>(x);
    float4* __restrict__ o4 = reinterpret_cast<float4*>(out);
    const int rowq = NF / 4;   // 64 float4 per feature row

    for (int pp = warp; pp < PPB; pp += 32) {
        const int hh = blockIdx.x * PPB + pp;
        const int a = sIdx[pp][0], b = sIdx[pp][1], c = sIdx[pp][2];
        const float w0 = sW[pp][0], w1 = sW[pp][1], w2 = sW[pp][2];
        const float4* __restrict__ ra = x4 + a * rowq;
        const float4* __restrict__ rb = x4 + b * rowq;
        const float4* __restrict__ rc = x4 + c * rowq;
        float4* __restrict__ ro = o4 + hh * rowq;
        #pragma unroll
        for (int ch = lane; ch < rowq; ch += 32) {
            const float4 va = ra[ch];
            const float4 vb = rb[ch];
            const float4 vc = rc[ch];
            float4 r;
            r.x = fmaf(w2, vc.x, fmaf(w1, vb.x, w0 * va.x));
            r.y = fmaf(w2, vc.y, fmaf(w1, vb.y, w0 * va.y));
            r.z = fmaf(w2, vc.z, fmaf(w1, vb.z, w0 * va.z));
            r.w = fmaf(w2, vc.w, fmaf(w1, vb.w, w0 * va.w));
            ro[ch] = r;
        }
    }
}

extern "C" void kernel_launch(void* const* d_in, const int* in_sizes, int n_in,
                              void* d_out, int out_size) {
    // Map inputs by element count:
    //   x: 4096*256 = 1048576, pos_l: 4096*3 = 12288, pos_h: 16384*3 = 49152
    const float* x     = nullptr;
    const float* pos_l = nullptr;
    const float* pos_h = nullptr;
    for (int i = 0; i < n_in; ++i) {
        if      (in_sizes[i] == NL * NF) x     = (const float*)d_in[i];
        else if (in_sizes[i] == NL * 3)  pos_l = (const float*)d_in[i];
        else if (in_sizes[i] == NH * 3)  pos_h = (const float*)d_in[i];
    }
    float* out = (float*)d_out;
    knn_interp_kernel<<<NH / PPB, TPB>>>(x, pos_l, pos_h, out);
}